// round 15
// baseline (speedup 1.0000x reference)
#include <cuda_runtime.h>
#include <cuda_bf16.h>
#include <math.h>
#include <cstdint>

// ---------------- problem constants ----------------
#define BB 2
#define SS 1024
#define DD 512
#define HH_ 8
#define DH 64
#define NTOK 2048           // B*S
#define NNEUR 512
#define KSEL 16
#define NBASIS 8
#define RANK 64
#define DFF 2048
#define LN_EPS 1e-5f

// ---------------- scratch (device globals; no allocation allowed) --------
__device__ float g_normed[NTOK * DD];
__device__ float g_q[NTOK * DD];
__device__ float g_k[NTOK * DD];
__device__ float g_v[NTOK * DD];
__device__ float g_ctx[NTOK * DD];
__device__ float g_ts[NTOK * NNEUR];
__device__ float g_cs[NTOK * NNEUR];
__device__ float g_x1[NTOK * DD];
__device__ float g_tc[NTOK * NBASIS];
__device__ float g_P[NTOK * (NBASIS * RANK)];
// bf16 FFN operands
__device__ __nv_bfloat16 g_n2bf[NTOK * DD];
__device__ __nv_bfloat16 g_HHbf[NTOK * (NBASIS * RANK)];
__device__ __nv_bfloat16 g_h2bf[(long)NTOK * DFF];
__device__ __nv_bfloat16 g_btA[NBASIS * RANK * DD];
__device__ __nv_bfloat16 g_btB[DFF * (NBASIS * RANK)];
__device__ __nv_bfloat16 g_btW[DD * DFF];

// ================= fp32 GEMM 128x64 tile, double buffered (1 sync/chunk) ==
#define FAS 132
#define FBS 68

__device__ __forceinline__ void gemm128_body(
    const float* __restrict__ A, int lda,
    const float* __restrict__ B, int ldb,
    float* __restrict__ C, int ldc,
    int m0, int n0, int Kd,
    const float* __restrict__ bias,
    int transB,
    float (*As)[16][FAS], float (*Bs)[16][FBS])
{
    int t = threadIdx.x;
    int tx = t & 15, ty = t >> 4;
    int r0 = t >> 2;
    int sg = (t & 3) * 4;

    const float* pA0 = A + (long)(m0 + r0) * lda + sg;
    const float* pA1 = A + (long)(m0 + r0 + 64) * lda + sg;
    const float* pBt = B + (long)(n0 + r0) * ldb + sg;
    const float* pBn = B + (long)(t >> 4) * ldb + n0 + tx * 4;

    float acc[8][4];
    #pragma unroll
    for (int i = 0; i < 8; i++)
        #pragma unroll
        for (int j = 0; j < 4; j++) acc[i][j] = 0.f;

    float4 ra0 = *(const float4*)pA0;
    float4 ra1 = *(const float4*)pA1;
    float4 rb  = transB ? *(const float4*)pBt : *(const float4*)pBn;

    int nk = Kd >> 4;
    for (int c = 0; c < nk; c++) {
        int buf = c & 1;
        As[buf][sg + 0][r0] = ra0.x; As[buf][sg + 1][r0] = ra0.y;
        As[buf][sg + 2][r0] = ra0.z; As[buf][sg + 3][r0] = ra0.w;
        As[buf][sg + 0][r0 + 64] = ra1.x; As[buf][sg + 1][r0 + 64] = ra1.y;
        As[buf][sg + 2][r0 + 64] = ra1.z; As[buf][sg + 3][r0 + 64] = ra1.w;
        if (transB) {
            Bs[buf][sg + 0][r0] = rb.x; Bs[buf][sg + 1][r0] = rb.y;
            Bs[buf][sg + 2][r0] = rb.z; Bs[buf][sg + 3][r0] = rb.w;
        } else {
            *(float4*)&Bs[buf][t >> 4][tx * 4] = rb;
        }
        __syncthreads();
        if (c + 1 < nk) {
            ra0 = *(const float4*)(pA0 + (c + 1) * 16);
            ra1 = *(const float4*)(pA1 + (c + 1) * 16);
            rb  = transB ? *(const float4*)(pBt + (c + 1) * 16)
                         : *(const float4*)(pBn + (long)(c + 1) * 16 * ldb);
        }
        #pragma unroll
        for (int kk = 0; kk < 16; kk++) {
            float4 a0 = *(const float4*)&As[buf][kk][ty * 8];
            float4 a1 = *(const float4*)&As[buf][kk][ty * 8 + 4];
            float4 b  = *(const float4*)&Bs[buf][kk][tx * 4];
            float av[8] = {a0.x, a0.y, a0.z, a0.w, a1.x, a1.y, a1.z, a1.w};
            float bv[4] = {b.x, b.y, b.z, b.w};
            #pragma unroll
            for (int i = 0; i < 8; i++)
                #pragma unroll
                for (int j = 0; j < 4; j++) acc[i][j] += av[i] * bv[j];
        }
    }

    float4 bb4 = make_float4(0.f, 0.f, 0.f, 0.f);
    if (bias) bb4 = *(const float4*)&bias[n0 + tx * 4];
    #pragma unroll
    for (int i = 0; i < 8; i++) {
        long gm = m0 + ty * 8 + i;
        float4 v = make_float4(acc[i][0] + bb4.x, acc[i][1] + bb4.y,
                               acc[i][2] + bb4.z, acc[i][3] + bb4.w);
        *(float4*)&C[gm * ldc + n0 + tx * 4] = v;
    }
}

// ---- QKV: grid (DD/64, NTOK/128, 3) ----
__global__ void __launch_bounds__(256) qkv128(
    const float* normed,
    const float* Wq, const float* Wk, const float* Wv,
    const float* bq, const float* bk, const float* bv,
    float* q, float* k, float* v)
{
    __shared__ float As[2][16][FAS];
    __shared__ float Bs[2][16][FBS];
    int z = blockIdx.z;
    const float* B = (z == 0) ? Wq : (z == 1) ? Wk : Wv;
    const float* bias = (z == 0) ? bq : (z == 1) ? bk : bv;
    float* C = (z == 0) ? q : (z == 1) ? k : v;
    gemm128_body(normed, DD, B, DD, C, DD,
                 blockIdx.y * 128, blockIdx.x * 64, DD, bias, 0, As, Bs);
}

// ---- neuron scores: grid (NNEUR/64, NTOK/128, 2), emb transB ----
__global__ void __launch_bounds__(256) ns128(
    const float* normed, const float* ctx, const float* emb,
    float* ts, float* cs)
{
    __shared__ float As[2][16][FAS];
    __shared__ float Bs[2][16][FBS];
    int z = blockIdx.z;
    const float* A = (z == 0) ? normed : ctx;
    float* C = (z == 0) ? ts : cs;
    gemm128_body(A, DD, emb, DD, C, NNEUR,
                 blockIdx.y * 128, blockIdx.x * 64, DD, nullptr, 1, As, Bs);
}

// ================= fused flash attention, 32-row query tiles ==============
// grid (16 heads, 32 q-tiles), 256 threads. Bitwise == previous versions:
// every output element accumulates keys ascending with exact-zero masks.
// smem: Qs[64][36] (k-major, 32 rows) | Ks[64][68] | Vs[64][68] | Ps[64][36]
#define QS 36
#define KT 68
__global__ void __launch_bounds__(256) attn_fused(
    const float* __restrict__ q, const float* __restrict__ k,
    const float* __restrict__ v, float* __restrict__ ctx)
{
    extern __shared__ float sm[];
    float (*Qs)[QS] = (float (*)[QS])sm;
    float (*Ks)[KT] = (float (*)[KT])(sm + 64 * QS);
    float (*Vs)[KT] = (float (*)[KT])(sm + 64 * QS + 64 * KT);
    float (*Ps)[QS] = (float (*)[QS])(sm + 64 * QS + 2 * 64 * KT);

    int z = blockIdx.x;                                    // head (b*8+h)
    int i0 = ((int)gridDim.y - 1 - (int)blockIdx.y) * 32;  // big tiles first
    long off = (long)(z >> 3) * SS * DD + (long)(z & 7) * DH;
    const float* Q = q + off;
    const float* K = k + off;
    const float* V = v + off;
    float* C = ctx + off;

    int t = threadIdx.x;
    int tx = t & 15, ty = t >> 4;          // ty: 2 rows, tx: 4 cols
    int r0 = t >> 2, sg = (t & 3) * 4;     // K loader (64 rows)
    int rq = t >> 3, cq = (t & 7) * 8;     // Q loader (32 rows)
    int vrow = t >> 4, vcol = tx * 4;      // V loader

    // load Q tile transposed: Qs[k][row]
    {
        float4 a = *(const float4*)(Q + (long)(i0 + rq) * DD + cq);
        float4 b = *(const float4*)(Q + (long)(i0 + rq) * DD + cq + 4);
        Qs[cq + 0][rq] = a.x; Qs[cq + 1][rq] = a.y;
        Qs[cq + 2][rq] = a.z; Qs[cq + 3][rq] = a.w;
        Qs[cq + 4][rq] = b.x; Qs[cq + 5][rq] = b.y;
        Qs[cq + 6][rq] = b.z; Qs[cq + 7][rq] = b.w;
    }

    float o[2][4];
    float asum[2];
    #pragma unroll
    for (int i = 0; i < 2; i++) {
        asum[i] = 0.f;
        #pragma unroll
        for (int j = 0; j < 4; j++) o[i][j] = 0.f;
    }

    for (int j0 = 0; j0 < i0 + 32; j0 += 64) {
        __syncthreads();   // Ks/Vs/Ps free (Qs ready on first iter)
        #pragma unroll
        for (int p = 0; p < 4; p++) {
            float4 a = *(const float4*)(K + (long)(j0 + r0) * DD + p * 16 + sg);
            Ks[p * 16 + sg + 0][r0] = a.x; Ks[p * 16 + sg + 1][r0] = a.y;
            Ks[p * 16 + sg + 2][r0] = a.z; Ks[p * 16 + sg + 3][r0] = a.w;
            *(float4*)&Vs[p * 16 + vrow][vcol] =
                *(const float4*)(V + (long)(j0 + p * 16 + vrow) * DD + vcol);
        }
        __syncthreads();

        // S = Q K^T over k=0..63 ascending
        float s[2][4];
        #pragma unroll
        for (int i = 0; i < 2; i++)
            #pragma unroll
            for (int j = 0; j < 4; j++) s[i][j] = 0.f;
        #pragma unroll
        for (int kk = 0; kk < 64; kk++) {
            float2 a2 = *(const float2*)&Qs[kk][ty * 2];
            float4 b4 = *(const float4*)&Ks[kk][tx * 4];
            float av[2] = {a2.x, a2.y};
            float bv[4] = {b4.x, b4.y, b4.z, b4.w};
            #pragma unroll
            for (int i = 0; i < 2; i++)
                #pragma unroll
                for (int j = 0; j < 4; j++) s[i][j] += av[i] * bv[j];
        }
        // mask + exp, stage Ps[key][row]
        #pragma unroll
        for (int j = 0; j < 4; j++) {
            int gk = j0 + tx * 4 + j;
            float2 pv;
            pv.x = (gk <= i0 + ty * 2 + 0) ? expf(s[0][j] * 0.125f) : 0.f;
            pv.y = (gk <= i0 + ty * 2 + 1) ? expf(s[1][j] * 0.125f) : 0.f;
            *(float2*)&Ps[tx * 4 + j][ty * 2] = pv;
        }
        __syncthreads();

        // O += P V, asum += P (keys ascending)
        #pragma unroll
        for (int kk = 0; kk < 64; kk++) {
            float2 a2 = *(const float2*)&Ps[kk][ty * 2];
            float4 b4 = *(const float4*)&Vs[kk][tx * 4];
            float av[2] = {a2.x, a2.y};
            float bv[4] = {b4.x, b4.y, b4.z, b4.w};
            #pragma unroll
            for (int i = 0; i < 2; i++) {
                #pragma unroll
                for (int j = 0; j < 4; j++) o[i][j] += av[i] * bv[j];
                asum[i] += av[i];
            }
        }
    }

    #pragma unroll
    for (int i = 0; i < 2; i++) {
        long gm = i0 + ty * 2 + i;
        float sI = 1.0f / asum[i];
        float4 vv = make_float4(o[i][0] * sI, o[i][1] * sI,
                                o[i][2] * sI, o[i][3] * sI);
        *(float4*)&C[gm * DD + tx * 4] = vv;
    }
}

// ================= bf16 MMA helpers =================
__device__ __forceinline__ uint32_t smem_u32(const void* p) {
    uint32_t a;
    asm("{ .reg .u64 t; cvta.to.shared.u64 t, %1; cvt.u32.u64 %0, t; }"
        : "=r"(a) : "l"(p));
    return a;
}
__device__ __forceinline__ void ldmatrix_x4(uint32_t& r0, uint32_t& r1,
                                            uint32_t& r2, uint32_t& r3,
                                            uint32_t addr)
{
    asm volatile("ldmatrix.sync.aligned.m8n8.x4.shared.b16 {%0,%1,%2,%3}, [%4];"
                 : "=r"(r0), "=r"(r1), "=r"(r2), "=r"(r3) : "r"(addr));
}
__device__ __forceinline__ void mma16816(float* c, const uint32_t* a,
                                         uint32_t b0, uint32_t b1)
{
    asm volatile(
        "mma.sync.aligned.m16n8k16.row.col.f32.bf16.bf16.f32 "
        "{%0,%1,%2,%3}, {%4,%5,%6,%7}, {%8,%9}, {%0,%1,%2,%3};"
        : "+f"(c[0]), "+f"(c[1]), "+f"(c[2]), "+f"(c[3])
        : "r"(a[0]), "r"(a[1]), "r"(a[2]), "r"(a[3]), "r"(b0), "r"(b1));
}

#define MT 128
#define NT 64
#define KC 32
#define SAS 40

// ---- bf16 GEMM, N-tile 64 (steps 7, 10) --------------------------------
__global__ void __launch_bounds__(256) mma_gemm(
    const __nv_bfloat16* __restrict__ Abf, int lda, long long sAz,
    const __nv_bfloat16* __restrict__ Bbf, int ldb, long long sBz,
    int Ktot,
    float* __restrict__ Cf, int ldc, long long sCz,
    const float* __restrict__ bias,
    const float* __restrict__ resid, int ldr,
    int mode)
{
    __shared__ __nv_bfloat16 sA[2][MT][SAS];
    __shared__ __nv_bfloat16 sB[2][NT][SAS];
    int tid = threadIdx.x, lane = tid & 31, wid = tid >> 5;
    int mw = wid & 3, nw = wid >> 2;
    long long z = blockIdx.z;
    const __nv_bfloat16* A = Abf + z * sAz + (long)(blockIdx.y * MT) * lda;
    const __nv_bfloat16* B = Bbf + z * sBz + (long)(blockIdx.x * NT) * ldb;

    int ar0 = tid >> 2, aseg = tid & 3;
    int br0 = tid >> 2, bseg = tid & 3;

    float acc[2][4][4];
    #pragma unroll
    for (int mi = 0; mi < 2; mi++)
        #pragma unroll
        for (int j = 0; j < 4; j++)
            #pragma unroll
            for (int e = 0; e < 4; e++) acc[mi][j][e] = 0.f;

    const uint4* pA0 = (const uint4*)(A + (long)ar0 * lda + aseg * 8);
    const uint4* pA1 = (const uint4*)(A + (long)(ar0 + 64) * lda + aseg * 8);
    const uint4* pB  = (const uint4*)(B + (long)br0 * ldb + bseg * 8);
    int stepA = KC / 8;

    uint4 ra0 = pA0[0], ra1 = pA1[0], rb = pB[0];

    int nk = Ktot / KC;
    for (int c = 0; c < nk; c++) {
        int buf = c & 1;
        *(uint4*)&sA[buf][ar0][aseg * 8]      = ra0;
        *(uint4*)&sA[buf][ar0 + 64][aseg * 8] = ra1;
        *(uint4*)&sB[buf][br0][bseg * 8]      = rb;
        __syncthreads();
        if (c + 1 < nk) {
            ra0 = pA0[(c + 1) * stepA];
            ra1 = pA1[(c + 1) * stepA];
            rb  = pB [(c + 1) * stepA];
        }
        #pragma unroll
        for (int ks = 0; ks < 2; ks++) {
            int k0 = ks * 16;
            int frow = lane & 15, fcol = k0 + (lane >> 4) * 8;
            uint32_t af[2][4];
            #pragma unroll
            for (int mi = 0; mi < 2; mi++) {
                uint32_t addr = smem_u32(&sA[buf][mw * 32 + mi * 16 + frow][fcol]);
                ldmatrix_x4(af[mi][0], af[mi][1], af[mi][2], af[mi][3], addr);
            }
            uint32_t bfr[2][4];
            #pragma unroll
            for (int bi = 0; bi < 2; bi++) {
                uint32_t addr = smem_u32(&sB[buf][nw * 32 + bi * 16 + frow][fcol]);
                ldmatrix_x4(bfr[bi][0], bfr[bi][1], bfr[bi][2], bfr[bi][3], addr);
            }
            #pragma unroll
            for (int mi = 0; mi < 2; mi++)
                #pragma unroll
                for (int j = 0; j < 4; j++)
                    mma16816(acc[mi][j], af[mi],
                             bfr[j >> 1][j & 1], bfr[j >> 1][2 + (j & 1)]);
        }
    }

    long gm_base = (long)blockIdx.y * MT + mw * 32;
    int  gn_base = blockIdx.x * NT + nw * 32;
    int  rr = lane >> 2, cc = (lane & 3) * 2;
    #pragma unroll
    for (int mi = 0; mi < 2; mi++) {
        #pragma unroll
        for (int j = 0; j < 4; j++) {
            int col = gn_base + j * 8 + cc;
            #pragma unroll
            for (int half = 0; half < 2; half++) {
                long row = gm_base + mi * 16 + rr + half * 8;
                float v0 = acc[mi][j][half * 2 + 0];
                float v1 = acc[mi][j][half * 2 + 1];
                if (mode == 0) {
                    *(float2*)&Cf[z * sCz + row * ldc + col] = make_float2(v0, v1);
                } else {
                    const float2 bb = *(const float2*)&bias[col];
                    const float2 rs = *(const float2*)&resid[row * ldr + col];
                    *(float2*)&Cf[z * sCz + row * ldc + col] =
                        make_float2(v0 + bb.x + rs.x, v1 + bb.y + rs.y);
                }
            }
        }
    }
}

// ---- bf16 GEMM, 128x128 tile (step 9: gelu -> bf16) ----------------------
__global__ void __launch_bounds__(256) mma_gemm_n128(
    const __nv_bfloat16* __restrict__ Abf, int lda,
    const __nv_bfloat16* __restrict__ Bbf, int ldb,
    int Ktot,
    __nv_bfloat16* __restrict__ Cbf, int ldc)
{
    __shared__ __nv_bfloat16 sA[2][128][SAS];
    __shared__ __nv_bfloat16 sB[2][128][SAS];
    int tid = threadIdx.x, lane = tid & 31, wid = tid >> 5;
    int mw = wid & 3, nw = wid >> 2;
    const __nv_bfloat16* A = Abf + (long)(blockIdx.y * 128) * lda;
    const __nv_bfloat16* B = Bbf + (long)(blockIdx.x * 128) * ldb;

    int r0 = tid >> 2, seg = tid & 3;

    float acc[2][8][4];
    #pragma unroll
    for (int mi = 0; mi < 2; mi++)
        #pragma unroll
        for (int j = 0; j < 8; j++)
            #pragma unroll
            for (int e = 0; e < 4; e++) acc[mi][j][e] = 0.f;

    const uint4* pA0 = (const uint4*)(A + (long)r0 * lda + seg * 8);
    const uint4* pA1 = (const uint4*)(A + (long)(r0 + 64) * lda + seg * 8);
    const uint4* pB0 = (const uint4*)(B + (long)r0 * ldb + seg * 8);
    const uint4* pB1 = (const uint4*)(B + (long)(r0 + 64) * ldb + seg * 8);
    int stepK = KC / 8;

    uint4 ra0 = pA0[0], ra1 = pA1[0], rb0 = pB0[0], rb1 = pB1[0];

    int nk = Ktot / KC;
    for (int c = 0; c < nk; c++) {
        int buf = c & 1;
        *(uint4*)&sA[buf][r0][seg * 8]      = ra0;
        *(uint4*)&sA[buf][r0 + 64][seg * 8] = ra1;
        *(uint4*)&sB[buf][r0][seg * 8]      = rb0;
        *(uint4*)&sB[buf][r0 + 64][seg * 8] = rb1;
        __syncthreads();
        if (c + 1 < nk) {
            ra0 = pA0[(c + 1) * stepK];
            ra1 = pA1[(c + 1) * stepK];
            rb0 = pB0[(c + 1) * stepK];
            rb1 = pB1[(c + 1) * stepK];
        }
        #pragma unroll
        for (int ks = 0; ks < 2; ks++) {
            int k0 = ks * 16;
            int frow = lane & 15, fcol = k0 + (lane >> 4) * 8;
            uint32_t af[2][4];
            #pragma unroll
            for (int mi = 0; mi < 2; mi++)
                ldmatrix_x4(af[mi][0], af[mi][1], af[mi][2], af[mi][3],
                            smem_u32(&sA[buf][mw * 32 + mi * 16 + frow][fcol]));
            uint32_t bfr[4][4];
            #pragma unroll
            for (int bi = 0; bi < 4; bi++)
                ldmatrix_x4(bfr[bi][0], bfr[bi][1], bfr[bi][2], bfr[bi][3],
                            smem_u32(&sB[buf][nw * 64 + bi * 16 + frow][fcol]));
            #pragma unroll
            for (int mi = 0; mi < 2; mi++)
                #pragma unroll
                for (int j = 0; j < 8; j++)
                    mma16816(acc[mi][j], af[mi],
                             bfr[j >> 1][j & 1], bfr[j >> 1][2 + (j & 1)]);
        }
    }

    long gm_base = (long)blockIdx.y * 128 + mw * 32;
    int  gn_base = blockIdx.x * 128 + nw * 64;
    int  rr = lane >> 2, cc = (lane & 3) * 2;
    #pragma unroll
    for (int mi = 0; mi < 2; mi++) {
        #pragma unroll
        for (int j = 0; j < 8; j++) {
            int col = gn_base + j * 8 + cc;
            #pragma unroll
            for (int half = 0; half < 2; half++) {
                long row = gm_base + mi * 16 + rr + half * 8;
                float v0 = acc[mi][j][half * 2 + 0];
                float v1 = acc[mi][j][half * 2 + 1];
                v0 = 0.5f * v0 * (1.0f + erff(v0 * 0.70710678118654752f));
                v1 = 0.5f * v1 * (1.0f + erff(v1 * 0.70710678118654752f));
                __nv_bfloat162 o;
                o.x = __float2bfloat16(v0);
                o.y = __float2bfloat16(v1);
                *(__nv_bfloat162*)&Cbf[row * ldc + col] = o;
            }
        }
    }
}

// ---------------- merged weight prep ----------
__device__ __forceinline__ void tr_tile(const float* __restrict__ in,
                                        __nv_bfloat16* __restrict__ outp,
                                        int R, int C, int bx, int by,
                                        float (*tile)[33])
{
    int c0 = bx * 32, r0 = by * 32;
    int tx = threadIdx.x, ty = threadIdx.y;
    #pragma unroll
    for (int i = ty; i < 32; i += 8)
        tile[i][tx] = in[(long)(r0 + i) * C + c0 + tx];
    __syncthreads();
    #pragma unroll
    for (int i = ty; i < 32; i += 8)
        outp[(long)(c0 + i) * R + r0 + tx] = __float2bfloat16(tile[tx][i]);
}

__global__ void prep_weights(const float* bA, const float* bBf, const float* Wd,
                             __nv_bfloat16* btA, __nv_bfloat16* btB,
                             __nv_bfloat16* btW)
{
    __shared__ float tile[32][33];
    int b = blockIdx.x;
    if (b < 256) {
        int z = b >> 5, rem = b & 31;
        tr_tile(bA + (long)z * 512 * 64, btA + (long)z * 64 * 512,
                512, 64, rem & 1, rem >> 1, tile);
    } else if (b < 1280) {
        int rem = b - 256;
        tr_tile(bBf, btB, 512, 2048, rem & 63, rem >> 6, tile);
    } else {
        int rem = b - 1280;
        tr_tile(Wd, btW, 2048, 512, rem & 15, rem >> 4, tile);
    }
}

// ---------------- LN1 ----------------
__global__ void ln_kernel(const float* __restrict__ x,
                          const float* __restrict__ g,
                          const float* __restrict__ b,
                          float* __restrict__ out)
{
    int token = blockIdx.x;
    const float* xr = x + (long)token * DD;
    int t = threadIdx.x;
    float v0 = xr[t], v1 = xr[t + 256];
    __shared__ float s1[256], s2[256];
    s1[t] = v0 + v1;
    s2[t] = v0 * v0 + v1 * v1;
    __syncthreads();
    for (int s = 128; s > 0; s >>= 1) {
        if (t < s) { s1[t] += s1[t + s]; s2[t] += s2[t + s]; }
        __syncthreads();
    }
    float mu  = s1[0] * (1.0f / DD);
    float var = s2[0] * (1.0f / DD) - mu * mu;
    float r = rsqrtf(var + LN_EPS);
    out[(long)token * DD + t]       = (v0 - mu) * r * g[t] + b[t];
    out[(long)token * DD + t + 256] = (v1 - mu) * r * g[t + 256] + b[t + 256];
}

// ------ fused: gate + score-mix + top-k + residual + coords + LN2 --------
__global__ void __launch_bounds__(256) topk_fused(
    const float* __restrict__ tok_s,
    const float* __restrict__ ctx_s,
    const float* __restrict__ normed,
    const float* __restrict__ ctx,
    const float* __restrict__ Wg,
    const float* __restrict__ bg,
    const float* __restrict__ x,
    const float* __restrict__ emb,
    const float* __restrict__ ncoords,
    const float* __restrict__ ln2g,
    const float* __restrict__ ln2b,
    float* __restrict__ x1,
    __nv_bfloat16* __restrict__ n2bf,
    float* __restrict__ coords_out,
    float* __restrict__ idx_out)
{
    int token = blockIdx.x;
    int t = threadIdx.x;
    int lane = t & 31, wid = t >> 5;
    __shared__ float sc[NNEUR];
    __shared__ float red2[256];
    __shared__ float wv[8];
    __shared__ int   wi[8];
    __shared__ int   sel_idx[KSEL];
    __shared__ float sel_val[KSEL];
    __shared__ float w[KSEL];
    __shared__ float gsh[2];

    // gate
    {
        float n0 = normed[(long)token * DD + t];
        float n1 = normed[(long)token * DD + t + 256];
        float c0 = ctx[(long)token * DD + t];
        float c1 = ctx[(long)token * DD + t + 256];
        float p0 = n0 * Wg[2 * t]             + n1 * Wg[2 * (t + 256)]
                 + c0 * Wg[2 * (DD + t)]      + c1 * Wg[2 * (DD + t + 256)];
        float p1 = n0 * Wg[2 * t + 1]         + n1 * Wg[2 * (t + 256) + 1]
                 + c0 * Wg[2 * (DD + t) + 1]  + c1 * Wg[2 * (DD + t + 256) + 1];
        sc[t] = p0; red2[t] = p1;
        __syncthreads();
        for (int s = 128; s > 0; s >>= 1) {
            if (t < s) { sc[t] += sc[t + s]; red2[t] += red2[t + s]; }
            __syncthreads();
        }
        if (t == 0) {
            float s0 = sc[0] + bg[0], s1v = red2[0] + bg[1];
            float m = fmaxf(s0, s1v);
            float e0 = expf(s0 - m), e1 = expf(s1v - m);
            float inv = 1.0f / (e0 + e1);
            gsh[0] = e0 * inv; gsh[1] = e1 * inv;
        }
        __syncthreads();
    }
    float g0 = gsh[0], g1 = gsh[1];

    // mixed scores
    sc[t]       = g0 * tok_s[(long)token * NNEUR + t]       + g1 * ctx_s[(long)token * NNEUR + t];
    sc[t + 256] = g0 * tok_s[(long)token * NNEUR + t + 256] + g1 * ctx_s[(long)token * NNEUR + t + 256];
    __syncthreads();

    // top-16 via shuffle argmax (tie -> lower index)
    for (int kk = 0; kk < KSEL; kk++) {
        float v = sc[t]; int idx = t;
        float v2 = sc[t + 256];
        if (v2 > v) { v = v2; idx = t + 256; }
        #pragma unroll
        for (int o = 16; o > 0; o >>= 1) {
            float ov = __shfl_down_sync(0xffffffffu, v, o);
            int   oi = __shfl_down_sync(0xffffffffu, idx, o);
            if (ov > v || (ov == v && oi < idx)) { v = ov; idx = oi; }
        }
        if (lane == 0) { wv[wid] = v; wi[wid] = idx; }
        __syncthreads();
        if (t == 0) {
            float bv = wv[0]; int bi = wi[0];
            #pragma unroll
            for (int ww = 1; ww < 8; ww++) {
                if (wv[ww] > bv || (wv[ww] == bv && wi[ww] < bi)) {
                    bv = wv[ww]; bi = wi[ww];
                }
            }
            sel_idx[kk] = bi;
            sel_val[kk] = bv;
            sc[bi] = -INFINITY;
        }
        __syncthreads();
    }
    if (t == 0) {
        float m = sel_val[0];
        float sum = 0.f;
        for (int kk = 0; kk < KSEL; kk++) { w[kk] = expf(sel_val[kk] - m); sum += w[kk]; }
        float inv = 1.0f / sum;
        for (int kk = 0; kk < KSEL; kk++) w[kk] *= inv;
    }
    __syncthreads();

    if (t < KSEL) idx_out[(long)token * KSEL + t] = (float)sel_idx[t];
    if (t < NBASIS) {
        float c = 0.f;
        for (int kk = 0; kk < KSEL; kk++) c += w[kk] * ncoords[(long)sel_idx[kk] * NBASIS + t];
        coords_out[(long)token * NBASIS + t] = c;
    }

    float a0 = x[(long)token * DD + t];
    float a1 = x[(long)token * DD + t + 256];
    #pragma unroll
    for (int kk = 0; kk < KSEL; kk++) {
        a0 += w[kk] * emb[(long)sel_idx[kk] * DD + t];
        a1 += w[kk] * emb[(long)sel_idx[kk] * DD + t + 256];
    }
    x1[(long)token * DD + t]       = a0;
    x1[(long)token * DD + t + 256] = a1;

    // LN2 -> bf16
    __syncthreads();
    sc[t]   = a0 + a1;
    red2[t] = a0 * a0 + a1 * a1;
    __syncthreads();
    for (int s = 128; s > 0; s >>= 1) {
        if (t < s) { sc[t] += sc[t + s]; red2[t] += red2[t + s]; }
        __syncthreads();
    }
    float mu  = sc[0] * (1.0f / DD);
    float var = red2[0] * (1.0f / DD) - mu * mu;
    float r = rsqrtf(var + LN_EPS);
    n2bf[(long)token * DD + t]       = __float2bfloat16((a0 - mu) * r * ln2g[t] + ln2b[t]);
    n2bf[(long)token * DD + t + 256] = __float2bfloat16((a1 - mu) * r * ln2g[t + 256] + ln2b[t + 256]);
}

// ---------------- combine ----------------
__global__ void combine_kernel(const float* __restrict__ P,
                               const float* __restrict__ coords,
                               __nv_bfloat16* __restrict__ HHo)
{
    int token = blockIdx.x;
    int r = threadIdx.x;
    __shared__ float c[NBASIS];
    if (r < NBASIS) c[r] = coords[(long)token * NBASIS + r];
    __syncthreads();
    float h = 0.f;
    #pragma unroll
    for (int n = 0; n < NBASIS; n++) h += c[n] * P[(long)token * 512 + n * RANK + r];
    #pragma unroll
    for (int n = 0; n < NBASIS; n++)
        HHo[(long)token * 512 + n * RANK + r] = __float2bfloat16(c[n] * h);
}

// ---------------- launch ----------------
extern "C" void kernel_launch(void* const* d_in, const int* in_sizes, int n_in,
                              void* d_out, int out_size)
{
    const float* x    = (const float*)d_in[0];
    const float* emb  = (const float*)d_in[1];
    const float* Wq   = (const float*)d_in[2];
    const float* bq   = (const float*)d_in[3];
    const float* Wk   = (const float*)d_in[4];
    const float* bk   = (const float*)d_in[5];
    const float* Wv   = (const float*)d_in[6];
    const float* bv   = (const float*)d_in[7];
    const float* Wg   = (const float*)d_in[8];
    const float* bg   = (const float*)d_in[9];
    const float* bA   = (const float*)d_in[10];
    const float* bBf  = (const float*)d_in[11];
    const float* ncd  = (const float*)d_in[12];
    const float* Wd   = (const float*)d_in[13];
    const float* bd   = (const float*)d_in[14];
    const float* ln1g = (const float*)d_in[15];
    const float* ln1b = (const float*)d_in[16];
    const float* ln2g = (const float*)d_in[17];
    const float* ln2b = (const float*)d_in[18];

    float* out     = (float*)d_out;
    float* out_idx = out + (long)NTOK * DD;

    float *normed, *q, *k, *v, *ctx, *ts, *cs, *x1, *tcv, *P;
    __nv_bfloat16 *n2bf, *HHbf, *h2bf, *btA, *btB, *btW;
    cudaGetSymbolAddress((void**)&normed, g_normed);
    cudaGetSymbolAddress((void**)&q, g_q);
    cudaGetSymbolAddress((void**)&k, g_k);
    cudaGetSymbolAddress((void**)&v, g_v);
    cudaGetSymbolAddress((void**)&ctx, g_ctx);
    cudaGetSymbolAddress((void**)&ts, g_ts);
    cudaGetSymbolAddress((void**)&cs, g_cs);
    cudaGetSymbolAddress((void**)&x1, g_x1);
    cudaGetSymbolAddress((void**)&tcv, g_tc);
    cudaGetSymbolAddress((void**)&P, g_P);
    cudaGetSymbolAddress((void**)&n2bf, g_n2bf);
    cudaGetSymbolAddress((void**)&HHbf, g_HHbf);
    cudaGetSymbolAddress((void**)&h2bf, g_h2bf);
    cudaGetSymbolAddress((void**)&btA, g_btA);
    cudaGetSymbolAddress((void**)&btB, g_btB);
    cudaGetSymbolAddress((void**)&btW, g_btW);

    // attn_fused dynamic smem: Qs + Ks + Vs + Ps
    static int smem_set = 0;
    const int ATTN_SMEM = (64 * QS + 2 * 64 * KT + 64 * QS) * (int)sizeof(float); // 53248
    if (!smem_set) {
        cudaFuncSetAttribute(attn_fused,
                             cudaFuncAttributeMaxDynamicSharedMemorySize,
                             ATTN_SMEM);
        smem_set = 1;
    }

    // FFN weight prep
    prep_weights<<<2304, dim3(32, 8)>>>(bA, bBf, Wd, btA, btB, btW);

    // 1. LN1 (fp32)
    ln_kernel<<<NTOK, 256>>>(x, ln1g, ln1b, normed);

    // 2. QKV (fp32)
    qkv128<<<dim3(DD / 64, NTOK / 128, 3), 256>>>(normed, Wq, Wk, Wv,
                                                  bq, bk, bv, q, k, v);

    // 3. fused flash attention, 32-row q-tiles (bitwise == prior rounds)
    attn_fused<<<dim3(BB * HH_, SS / 32), 256, ATTN_SMEM>>>(q, k, v, ctx);

    // 4. neuron scores (fp32, z=2)
    ns128<<<dim3(NNEUR / 64, NTOK / 128, 2), 256>>>(normed, ctx, emb, ts, cs);

    // 5. fused gate + topk + residual + coords + LN2
    topk_fused<<<NTOK, 256>>>(ts, cs, normed, ctx, Wg, bg, x, emb, ncd,
                              ln2g, ln2b, x1, n2bf, tcv, out_idx);

    // 7. P = n2 @ A_n (bf16 mma, batched over n)
    mma_gemm<<<dim3(1, NTOK / MT, NBASIS), 256>>>(
        n2bf, DD, 0, btA, DD, (long long)RANK * DD, DD,
        P, NBASIS * RANK, RANK, nullptr, nullptr, 0, 0);

    // 8. combine -> HH (bf16)
    combine_kernel<<<NTOK, 64>>>(P, tcv, HHbf);

    // 9. h2 = gelu(HH @ B_flat) (bf16 mma, 128x128 tiles)
    mma_gemm_n128<<<dim3(DFF / 128, NTOK / 128), 256>>>(
        HHbf, NBASIS * RANK, btB, NBASIS * RANK, NBASIS * RANK, h2bf, DFF);

    // 10. out = h2 @ Wd + bd + x1 (bf16 mma)
    mma_gemm<<<dim3(DD / NT, NTOK / MT, 1), 256>>>(
        h2bf, DFF, 0, btW, DFF, 0, DFF,
        out, DD, 0, bd, x1, DD, 2);
}

// round 16
// speedup vs baseline: 1.0881x; 1.0881x over previous
#include <cuda_runtime.h>
#include <cuda_bf16.h>
#include <math.h>
#include <cstdint>

// ---------------- problem constants ----------------
#define BB 2
#define SS 1024
#define DD 512
#define HH_ 8
#define DH 64
#define NTOK 2048           // B*S
#define NNEUR 512
#define KSEL 16
#define NBASIS 8
#define RANK 64
#define DFF 2048
#define LN_EPS 1e-5f

// ---------------- scratch (device globals; no allocation allowed) --------
__device__ float g_normed[NTOK * DD];
__device__ float g_q[NTOK * DD];
__device__ float g_k[NTOK * DD];
__device__ float g_v[NTOK * DD];
__device__ float g_ctx[NTOK * DD];
__device__ float g_ts[NTOK * NNEUR];
__device__ float g_cs[NTOK * NNEUR];
__device__ float g_x1[NTOK * DD];
__device__ float g_tc[NTOK * NBASIS];
__device__ float g_P[NTOK * (NBASIS * RANK)];
// bf16 FFN operands
__device__ __nv_bfloat16 g_n2bf[NTOK * DD];
__device__ __nv_bfloat16 g_HHbf[NTOK * (NBASIS * RANK)];
__device__ __nv_bfloat16 g_h2bf[(long)NTOK * DFF];
__device__ __nv_bfloat16 g_btA[NBASIS * RANK * DD];
__device__ __nv_bfloat16 g_btB[DFF * (NBASIS * RANK)];
__device__ __nv_bfloat16 g_btW[DD * DFF];

// ================= fp32 GEMM 128x64 tile, double buffered (1 sync/chunk) ==
#define FAS 132
#define FBS 68

__device__ __forceinline__ void gemm128_body(
    const float* __restrict__ A, int lda,
    const float* __restrict__ B, int ldb,
    float* __restrict__ C, int ldc,
    int m0, int n0, int Kd,
    const float* __restrict__ bias,
    int transB,
    float (*As)[16][FAS], float (*Bs)[16][FBS])
{
    int t = threadIdx.x;
    int tx = t & 15, ty = t >> 4;
    int r0 = t >> 2;
    int sg = (t & 3) * 4;

    const float* pA0 = A + (long)(m0 + r0) * lda + sg;
    const float* pA1 = A + (long)(m0 + r0 + 64) * lda + sg;
    const float* pBt = B + (long)(n0 + r0) * ldb + sg;
    const float* pBn = B + (long)(t >> 4) * ldb + n0 + tx * 4;

    float acc[8][4];
    #pragma unroll
    for (int i = 0; i < 8; i++)
        #pragma unroll
        for (int j = 0; j < 4; j++) acc[i][j] = 0.f;

    float4 ra0 = *(const float4*)pA0;
    float4 ra1 = *(const float4*)pA1;
    float4 rb  = transB ? *(const float4*)pBt : *(const float4*)pBn;

    int nk = Kd >> 4;
    for (int c = 0; c < nk; c++) {
        int buf = c & 1;
        As[buf][sg + 0][r0] = ra0.x; As[buf][sg + 1][r0] = ra0.y;
        As[buf][sg + 2][r0] = ra0.z; As[buf][sg + 3][r0] = ra0.w;
        As[buf][sg + 0][r0 + 64] = ra1.x; As[buf][sg + 1][r0 + 64] = ra1.y;
        As[buf][sg + 2][r0 + 64] = ra1.z; As[buf][sg + 3][r0 + 64] = ra1.w;
        if (transB) {
            Bs[buf][sg + 0][r0] = rb.x; Bs[buf][sg + 1][r0] = rb.y;
            Bs[buf][sg + 2][r0] = rb.z; Bs[buf][sg + 3][r0] = rb.w;
        } else {
            *(float4*)&Bs[buf][t >> 4][tx * 4] = rb;
        }
        __syncthreads();
        if (c + 1 < nk) {
            ra0 = *(const float4*)(pA0 + (c + 1) * 16);
            ra1 = *(const float4*)(pA1 + (c + 1) * 16);
            rb  = transB ? *(const float4*)(pBt + (c + 1) * 16)
                         : *(const float4*)(pBn + (long)(c + 1) * 16 * ldb);
        }
        #pragma unroll
        for (int kk = 0; kk < 16; kk++) {
            float4 a0 = *(const float4*)&As[buf][kk][ty * 8];
            float4 a1 = *(const float4*)&As[buf][kk][ty * 8 + 4];
            float4 b  = *(const float4*)&Bs[buf][kk][tx * 4];
            float av[8] = {a0.x, a0.y, a0.z, a0.w, a1.x, a1.y, a1.z, a1.w};
            float bv[4] = {b.x, b.y, b.z, b.w};
            #pragma unroll
            for (int i = 0; i < 8; i++)
                #pragma unroll
                for (int j = 0; j < 4; j++) acc[i][j] += av[i] * bv[j];
        }
    }

    float4 bb4 = make_float4(0.f, 0.f, 0.f, 0.f);
    if (bias) bb4 = *(const float4*)&bias[n0 + tx * 4];
    #pragma unroll
    for (int i = 0; i < 8; i++) {
        long gm = m0 + ty * 8 + i;
        float4 v = make_float4(acc[i][0] + bb4.x, acc[i][1] + bb4.y,
                               acc[i][2] + bb4.z, acc[i][3] + bb4.w);
        *(float4*)&C[gm * ldc + n0 + tx * 4] = v;
    }
}

// ---- QKV: grid (DD/64, NTOK/128, 3) ----
__global__ void __launch_bounds__(256) qkv128(
    const float* normed,
    const float* Wq, const float* Wk, const float* Wv,
    const float* bq, const float* bk, const float* bv,
    float* q, float* k, float* v)
{
    __shared__ float As[2][16][FAS];
    __shared__ float Bs[2][16][FBS];
    int z = blockIdx.z;
    const float* B = (z == 0) ? Wq : (z == 1) ? Wk : Wv;
    const float* bias = (z == 0) ? bq : (z == 1) ? bk : bv;
    float* C = (z == 0) ? q : (z == 1) ? k : v;
    gemm128_body(normed, DD, B, DD, C, DD,
                 blockIdx.y * 128, blockIdx.x * 64, DD, bias, 0, As, Bs);
}

// ---- neuron scores: grid (NNEUR/64, NTOK/128, 2), emb transB ----
__global__ void __launch_bounds__(256) ns128(
    const float* normed, const float* ctx, const float* emb,
    float* ts, float* cs)
{
    __shared__ float As[2][16][FAS];
    __shared__ float Bs[2][16][FBS];
    int z = blockIdx.z;
    const float* A = (z == 0) ? normed : ctx;
    float* C = (z == 0) ? ts : cs;
    gemm128_body(A, DD, emb, DD, C, NNEUR,
                 blockIdx.y * 128, blockIdx.x * 64, DD, nullptr, 1, As, Bs);
}

// ================= fused flash attention, 64-row tiles + reg prefetch =====
// grid (16 heads, 16 q-tiles), 256 threads. Bitwise == R13/R14.
#define FT 68
__global__ void __launch_bounds__(256) attn_fused(
    const float* __restrict__ q, const float* __restrict__ k,
    const float* __restrict__ v, float* __restrict__ ctx)
{
    extern __shared__ float sm[];
    float (*Qs)[FT] = (float (*)[FT])sm;
    float (*Ks)[FT] = (float (*)[FT])(sm + 64 * FT);
    float (*Vs)[FT] = (float (*)[FT])(sm + 2 * 64 * FT);
    float (*Ps)[FT] = (float (*)[FT])(sm + 3 * 64 * FT);

    int z = blockIdx.x;                                  // head (b*8+h)
    int i0 = ((int)gridDim.y - 1 - (int)blockIdx.y) * 64; // big tiles first
    long off = (long)(z >> 3) * SS * DD + (long)(z & 7) * DH;
    const float* Q = q + off;
    const float* K = k + off;
    const float* V = v + off;
    float* C = ctx + off;

    int t = threadIdx.x;
    int tx = t & 15, ty = t >> 4;
    int r0 = t >> 2, sg = (t & 3) * 4;
    int vrow = t >> 4, vcol = tx * 4;

    // prefetch K/V tile 0 into registers
    float4 rk[4], rv[4];
    #pragma unroll
    for (int p = 0; p < 4; p++) {
        rk[p] = *(const float4*)(K + (long)r0 * DD + p * 16 + sg);
        rv[p] = *(const float4*)(V + (long)(p * 16 + vrow) * DD + vcol);
    }

    // load Q tile transposed: Qs[k][row]
    #pragma unroll
    for (int p = 0; p < 4; p++) {
        float4 a = *(const float4*)(Q + (long)(i0 + r0) * DD + p * 16 + sg);
        Qs[p * 16 + sg + 0][r0] = a.x; Qs[p * 16 + sg + 1][r0] = a.y;
        Qs[p * 16 + sg + 2][r0] = a.z; Qs[p * 16 + sg + 3][r0] = a.w;
    }

    float o[4][4];
    float asum[4];
    #pragma unroll
    for (int i = 0; i < 4; i++) {
        asum[i] = 0.f;
        #pragma unroll
        for (int j = 0; j < 4; j++) o[i][j] = 0.f;
    }

    for (int j0 = 0; j0 <= i0; j0 += 64) {
        __syncthreads();   // Ks/Vs/Ps free (Qs ready on first iter)
        // commit prefetched K (transposed) and V tiles to SMEM
        #pragma unroll
        for (int p = 0; p < 4; p++) {
            Ks[p * 16 + sg + 0][r0] = rk[p].x; Ks[p * 16 + sg + 1][r0] = rk[p].y;
            Ks[p * 16 + sg + 2][r0] = rk[p].z; Ks[p * 16 + sg + 3][r0] = rk[p].w;
            *(float4*)&Vs[p * 16 + vrow][vcol] = rv[p];
        }
        __syncthreads();
        // prefetch next K/V tile (latency hidden behind S + PV compute)
        if (j0 + 64 <= i0) {
            #pragma unroll
            for (int p = 0; p < 4; p++) {
                rk[p] = *(const float4*)(K + (long)(j0 + 64 + r0) * DD + p * 16 + sg);
                rv[p] = *(const float4*)(V + (long)(j0 + 64 + p * 16 + vrow) * DD + vcol);
            }
        }

        // S = Q K^T over k=0..63 ascending (same order as prior rounds)
        float s[4][4];
        #pragma unroll
        for (int i = 0; i < 4; i++)
            #pragma unroll
            for (int j = 0; j < 4; j++) s[i][j] = 0.f;
        #pragma unroll
        for (int kk = 0; kk < 64; kk++) {
            float4 a4 = *(const float4*)&Qs[kk][ty * 4];
            float4 b4 = *(const float4*)&Ks[kk][tx * 4];
            float av[4] = {a4.x, a4.y, a4.z, a4.w};
            float bv[4] = {b4.x, b4.y, b4.z, b4.w};
            #pragma unroll
            for (int i = 0; i < 4; i++)
                #pragma unroll
                for (int j = 0; j < 4; j++) s[i][j] += av[i] * bv[j];
        }
        // mask + exp, stage to Ps[key][row]
        #pragma unroll
        for (int j = 0; j < 4; j++) {
            int gk = j0 + tx * 4 + j;
            float4 pv;
            pv.x = (gk <= i0 + ty * 4 + 0) ? expf(s[0][j] * 0.125f) : 0.f;
            pv.y = (gk <= i0 + ty * 4 + 1) ? expf(s[1][j] * 0.125f) : 0.f;
            pv.z = (gk <= i0 + ty * 4 + 2) ? expf(s[2][j] * 0.125f) : 0.f;
            pv.w = (gk <= i0 + ty * 4 + 3) ? expf(s[3][j] * 0.125f) : 0.f;
            *(float4*)&Ps[tx * 4 + j][ty * 4] = pv;
        }
        __syncthreads();

        // O += P V, asum += P (keys ascending)
        #pragma unroll
        for (int kk = 0; kk < 64; kk++) {
            float4 a4 = *(const float4*)&Ps[kk][ty * 4];
            float4 b4 = *(const float4*)&Vs[kk][tx * 4];
            float av[4] = {a4.x, a4.y, a4.z, a4.w};
            float bv[4] = {b4.x, b4.y, b4.z, b4.w};
            #pragma unroll
            for (int i = 0; i < 4; i++) {
                #pragma unroll
                for (int j = 0; j < 4; j++) o[i][j] += av[i] * bv[j];
                asum[i] += av[i];
            }
        }
    }

    #pragma unroll
    for (int i = 0; i < 4; i++) {
        long gm = i0 + ty * 4 + i;
        float sI = 1.0f / asum[i];
        float4 vv = make_float4(o[i][0] * sI, o[i][1] * sI,
                                o[i][2] * sI, o[i][3] * sI);
        *(float4*)&C[gm * DD + tx * 4] = vv;
    }
}

// ================= bf16 MMA helpers =================
__device__ __forceinline__ uint32_t smem_u32(const void* p) {
    uint32_t a;
    asm("{ .reg .u64 t; cvta.to.shared.u64 t, %1; cvt.u32.u64 %0, t; }"
        : "=r"(a) : "l"(p));
    return a;
}
__device__ __forceinline__ void ldmatrix_x4(uint32_t& r0, uint32_t& r1,
                                            uint32_t& r2, uint32_t& r3,
                                            uint32_t addr)
{
    asm volatile("ldmatrix.sync.aligned.m8n8.x4.shared.b16 {%0,%1,%2,%3}, [%4];"
                 : "=r"(r0), "=r"(r1), "=r"(r2), "=r"(r3) : "r"(addr));
}
__device__ __forceinline__ void mma16816(float* c, const uint32_t* a,
                                         uint32_t b0, uint32_t b1)
{
    asm volatile(
        "mma.sync.aligned.m16n8k16.row.col.f32.bf16.bf16.f32 "
        "{%0,%1,%2,%3}, {%4,%5,%6,%7}, {%8,%9}, {%0,%1,%2,%3};"
        : "+f"(c[0]), "+f"(c[1]), "+f"(c[2]), "+f"(c[3])
        : "r"(a[0]), "r"(a[1]), "r"(a[2]), "r"(a[3]), "r"(b0), "r"(b1));
}

#define MT 128
#define NT 64
#define KC 32
#define SAS 40

// ---- bf16 GEMM, N-tile 64 (steps 7, 10) --------------------------------
__global__ void __launch_bounds__(256) mma_gemm(
    const __nv_bfloat16* __restrict__ Abf, int lda, long long sAz,
    const __nv_bfloat16* __restrict__ Bbf, int ldb, long long sBz,
    int Ktot,
    float* __restrict__ Cf, int ldc, long long sCz,
    const float* __restrict__ bias,
    const float* __restrict__ resid, int ldr,
    int mode)
{
    __shared__ __nv_bfloat16 sA[2][MT][SAS];
    __shared__ __nv_bfloat16 sB[2][NT][SAS];
    int tid = threadIdx.x, lane = tid & 31, wid = tid >> 5;
    int mw = wid & 3, nw = wid >> 2;
    long long z = blockIdx.z;
    const __nv_bfloat16* A = Abf + z * sAz + (long)(blockIdx.y * MT) * lda;
    const __nv_bfloat16* B = Bbf + z * sBz + (long)(blockIdx.x * NT) * ldb;

    int ar0 = tid >> 2, aseg = tid & 3;
    int br0 = tid >> 2, bseg = tid & 3;

    float acc[2][4][4];
    #pragma unroll
    for (int mi = 0; mi < 2; mi++)
        #pragma unroll
        for (int j = 0; j < 4; j++)
            #pragma unroll
            for (int e = 0; e < 4; e++) acc[mi][j][e] = 0.f;

    const uint4* pA0 = (const uint4*)(A + (long)ar0 * lda + aseg * 8);
    const uint4* pA1 = (const uint4*)(A + (long)(ar0 + 64) * lda + aseg * 8);
    const uint4* pB  = (const uint4*)(B + (long)br0 * ldb + bseg * 8);
    int stepA = KC / 8;

    uint4 ra0 = pA0[0], ra1 = pA1[0], rb = pB[0];

    int nk = Ktot / KC;
    for (int c = 0; c < nk; c++) {
        int buf = c & 1;
        *(uint4*)&sA[buf][ar0][aseg * 8]      = ra0;
        *(uint4*)&sA[buf][ar0 + 64][aseg * 8] = ra1;
        *(uint4*)&sB[buf][br0][bseg * 8]      = rb;
        __syncthreads();
        if (c + 1 < nk) {
            ra0 = pA0[(c + 1) * stepA];
            ra1 = pA1[(c + 1) * stepA];
            rb  = pB [(c + 1) * stepA];
        }
        #pragma unroll
        for (int ks = 0; ks < 2; ks++) {
            int k0 = ks * 16;
            int frow = lane & 15, fcol = k0 + (lane >> 4) * 8;
            uint32_t af[2][4];
            #pragma unroll
            for (int mi = 0; mi < 2; mi++) {
                uint32_t addr = smem_u32(&sA[buf][mw * 32 + mi * 16 + frow][fcol]);
                ldmatrix_x4(af[mi][0], af[mi][1], af[mi][2], af[mi][3], addr);
            }
            uint32_t bfr[2][4];
            #pragma unroll
            for (int bi = 0; bi < 2; bi++) {
                uint32_t addr = smem_u32(&sB[buf][nw * 32 + bi * 16 + frow][fcol]);
                ldmatrix_x4(bfr[bi][0], bfr[bi][1], bfr[bi][2], bfr[bi][3], addr);
            }
            #pragma unroll
            for (int mi = 0; mi < 2; mi++)
                #pragma unroll
                for (int j = 0; j < 4; j++)
                    mma16816(acc[mi][j], af[mi],
                             bfr[j >> 1][j & 1], bfr[j >> 1][2 + (j & 1)]);
        }
    }

    long gm_base = (long)blockIdx.y * MT + mw * 32;
    int  gn_base = blockIdx.x * NT + nw * 32;
    int  rr = lane >> 2, cc = (lane & 3) * 2;
    #pragma unroll
    for (int mi = 0; mi < 2; mi++) {
        #pragma unroll
        for (int j = 0; j < 4; j++) {
            int col = gn_base + j * 8 + cc;
            #pragma unroll
            for (int half = 0; half < 2; half++) {
                long row = gm_base + mi * 16 + rr + half * 8;
                float v0 = acc[mi][j][half * 2 + 0];
                float v1 = acc[mi][j][half * 2 + 1];
                if (mode == 0) {
                    *(float2*)&Cf[z * sCz + row * ldc + col] = make_float2(v0, v1);
                } else {
                    const float2 bb = *(const float2*)&bias[col];
                    const float2 rs = *(const float2*)&resid[row * ldr + col];
                    *(float2*)&Cf[z * sCz + row * ldc + col] =
                        make_float2(v0 + bb.x + rs.x, v1 + bb.y + rs.y);
                }
            }
        }
    }
}

// ---- bf16 GEMM, 128x128 tile (step 9: gelu -> bf16) ----------------------
__global__ void __launch_bounds__(256) mma_gemm_n128(
    const __nv_bfloat16* __restrict__ Abf, int lda,
    const __nv_bfloat16* __restrict__ Bbf, int ldb,
    int Ktot,
    __nv_bfloat16* __restrict__ Cbf, int ldc)
{
    __shared__ __nv_bfloat16 sA[2][128][SAS];
    __shared__ __nv_bfloat16 sB[2][128][SAS];
    int tid = threadIdx.x, lane = tid & 31, wid = tid >> 5;
    int mw = wid & 3, nw = wid >> 2;
    const __nv_bfloat16* A = Abf + (long)(blockIdx.y * 128) * lda;
    const __nv_bfloat16* B = Bbf + (long)(blockIdx.x * 128) * ldb;

    int r0 = tid >> 2, seg = tid & 3;

    float acc[2][8][4];
    #pragma unroll
    for (int mi = 0; mi < 2; mi++)
        #pragma unroll
        for (int j = 0; j < 8; j++)
            #pragma unroll
            for (int e = 0; e < 4; e++) acc[mi][j][e] = 0.f;

    const uint4* pA0 = (const uint4*)(A + (long)r0 * lda + seg * 8);
    const uint4* pA1 = (const uint4*)(A + (long)(r0 + 64) * lda + seg * 8);
    const uint4* pB0 = (const uint4*)(B + (long)r0 * ldb + seg * 8);
    const uint4* pB1 = (const uint4*)(B + (long)(r0 + 64) * ldb + seg * 8);
    int stepK = KC / 8;

    uint4 ra0 = pA0[0], ra1 = pA1[0], rb0 = pB0[0], rb1 = pB1[0];

    int nk = Ktot / KC;
    for (int c = 0; c < nk; c++) {
        int buf = c & 1;
        *(uint4*)&sA[buf][r0][seg * 8]      = ra0;
        *(uint4*)&sA[buf][r0 + 64][seg * 8] = ra1;
        *(uint4*)&sB[buf][r0][seg * 8]      = rb0;
        *(uint4*)&sB[buf][r0 + 64][seg * 8] = rb1;
        __syncthreads();
        if (c + 1 < nk) {
            ra0 = pA0[(c + 1) * stepK];
            ra1 = pA1[(c + 1) * stepK];
            rb0 = pB0[(c + 1) * stepK];
            rb1 = pB1[(c + 1) * stepK];
        }
        #pragma unroll
        for (int ks = 0; ks < 2; ks++) {
            int k0 = ks * 16;
            int frow = lane & 15, fcol = k0 + (lane >> 4) * 8;
            uint32_t af[2][4];
            #pragma unroll
            for (int mi = 0; mi < 2; mi++)
                ldmatrix_x4(af[mi][0], af[mi][1], af[mi][2], af[mi][3],
                            smem_u32(&sA[buf][mw * 32 + mi * 16 + frow][fcol]));
            uint32_t bfr[4][4];
            #pragma unroll
            for (int bi = 0; bi < 4; bi++)
                ldmatrix_x4(bfr[bi][0], bfr[bi][1], bfr[bi][2], bfr[bi][3],
                            smem_u32(&sB[buf][nw * 64 + bi * 16 + frow][fcol]));
            #pragma unroll
            for (int mi = 0; mi < 2; mi++)
                #pragma unroll
                for (int j = 0; j < 8; j++)
                    mma16816(acc[mi][j], af[mi],
                             bfr[j >> 1][j & 1], bfr[j >> 1][2 + (j & 1)]);
        }
    }

    long gm_base = (long)blockIdx.y * 128 + mw * 32;
    int  gn_base = blockIdx.x * 128 + nw * 64;
    int  rr = lane >> 2, cc = (lane & 3) * 2;
    #pragma unroll
    for (int mi = 0; mi < 2; mi++) {
        #pragma unroll
        for (int j = 0; j < 8; j++) {
            int col = gn_base + j * 8 + cc;
            #pragma unroll
            for (int half = 0; half < 2; half++) {
                long row = gm_base + mi * 16 + rr + half * 8;
                float v0 = acc[mi][j][half * 2 + 0];
                float v1 = acc[mi][j][half * 2 + 1];
                v0 = 0.5f * v0 * (1.0f + erff(v0 * 0.70710678118654752f));
                v1 = 0.5f * v1 * (1.0f + erff(v1 * 0.70710678118654752f));
                __nv_bfloat162 o;
                o.x = __float2bfloat16(v0);
                o.y = __float2bfloat16(v1);
                *(__nv_bfloat162*)&Cbf[row * ldc + col] = o;
            }
        }
    }
}

// ---------------- merged weight prep ----------
__device__ __forceinline__ void tr_tile(const float* __restrict__ in,
                                        __nv_bfloat16* __restrict__ outp,
                                        int R, int C, int bx, int by,
                                        float (*tile)[33])
{
    int c0 = bx * 32, r0 = by * 32;
    int tx = threadIdx.x, ty = threadIdx.y;
    #pragma unroll
    for (int i = ty; i < 32; i += 8)
        tile[i][tx] = in[(long)(r0 + i) * C + c0 + tx];
    __syncthreads();
    #pragma unroll
    for (int i = ty; i < 32; i += 8)
        outp[(long)(c0 + i) * R + r0 + tx] = __float2bfloat16(tile[tx][i]);
}

__global__ void prep_weights(const float* bA, const float* bBf, const float* Wd,
                             __nv_bfloat16* btA, __nv_bfloat16* btB,
                             __nv_bfloat16* btW)
{
    __shared__ float tile[32][33];
    int b = blockIdx.x;
    if (b < 256) {
        int z = b >> 5, rem = b & 31;
        tr_tile(bA + (long)z * 512 * 64, btA + (long)z * 64 * 512,
                512, 64, rem & 1, rem >> 1, tile);
    } else if (b < 1280) {
        int rem = b - 256;
        tr_tile(bBf, btB, 512, 2048, rem & 63, rem >> 6, tile);
    } else {
        int rem = b - 1280;
        tr_tile(Wd, btW, 2048, 512, rem & 15, rem >> 4, tile);
    }
}

// ---------------- LN1 ----------------
__global__ void ln_kernel(const float* __restrict__ x,
                          const float* __restrict__ g,
                          const float* __restrict__ b,
                          float* __restrict__ out)
{
    int token = blockIdx.x;
    const float* xr = x + (long)token * DD;
    int t = threadIdx.x;
    float v0 = xr[t], v1 = xr[t + 256];
    __shared__ float s1[256], s2[256];
    s1[t] = v0 + v1;
    s2[t] = v0 * v0 + v1 * v1;
    __syncthreads();
    for (int s = 128; s > 0; s >>= 1) {
        if (t < s) { s1[t] += s1[t + s]; s2[t] += s2[t + s]; }
        __syncthreads();
    }
    float mu  = s1[0] * (1.0f / DD);
    float var = s2[0] * (1.0f / DD) - mu * mu;
    float r = rsqrtf(var + LN_EPS);
    out[(long)token * DD + t]       = (v0 - mu) * r * g[t] + b[t];
    out[(long)token * DD + t + 256] = (v1 - mu) * r * g[t + 256] + b[t + 256];
}

// ------ fused: gate + score-mix + top-k + residual + coords + LN2 --------
__global__ void __launch_bounds__(256) topk_fused(
    const float* __restrict__ tok_s,
    const float* __restrict__ ctx_s,
    const float* __restrict__ normed,
    const float* __restrict__ ctx,
    const float* __restrict__ Wg,
    const float* __restrict__ bg,
    const float* __restrict__ x,
    const float* __restrict__ emb,
    const float* __restrict__ ncoords,
    const float* __restrict__ ln2g,
    const float* __restrict__ ln2b,
    float* __restrict__ x1,
    __nv_bfloat16* __restrict__ n2bf,
    float* __restrict__ coords_out,
    float* __restrict__ idx_out)
{
    int token = blockIdx.x;
    int t = threadIdx.x;
    int lane = t & 31, wid = t >> 5;
    __shared__ float sc[NNEUR];
    __shared__ float red2[256];
    __shared__ float wv[8];
    __shared__ int   wi[8];
    __shared__ int   sel_idx[KSEL];
    __shared__ float sel_val[KSEL];
    __shared__ float w[KSEL];
    __shared__ float gsh[2];

    // gate
    {
        float n0 = normed[(long)token * DD + t];
        float n1 = normed[(long)token * DD + t + 256];
        float c0 = ctx[(long)token * DD + t];
        float c1 = ctx[(long)token * DD + t + 256];
        float p0 = n0 * Wg[2 * t]             + n1 * Wg[2 * (t + 256)]
                 + c0 * Wg[2 * (DD + t)]      + c1 * Wg[2 * (DD + t + 256)];
        float p1 = n0 * Wg[2 * t + 1]         + n1 * Wg[2 * (t + 256) + 1]
                 + c0 * Wg[2 * (DD + t) + 1]  + c1 * Wg[2 * (DD + t + 256) + 1];
        sc[t] = p0; red2[t] = p1;
        __syncthreads();
        for (int s = 128; s > 0; s >>= 1) {
            if (t < s) { sc[t] += sc[t + s]; red2[t] += red2[t + s]; }
            __syncthreads();
        }
        if (t == 0) {
            float s0 = sc[0] + bg[0], s1v = red2[0] + bg[1];
            float m = fmaxf(s0, s1v);
            float e0 = expf(s0 - m), e1 = expf(s1v - m);
            float inv = 1.0f / (e0 + e1);
            gsh[0] = e0 * inv; gsh[1] = e1 * inv;
        }
        __syncthreads();
    }
    float g0 = gsh[0], g1 = gsh[1];

    // mixed scores
    sc[t]       = g0 * tok_s[(long)token * NNEUR + t]       + g1 * ctx_s[(long)token * NNEUR + t];
    sc[t + 256] = g0 * tok_s[(long)token * NNEUR + t + 256] + g1 * ctx_s[(long)token * NNEUR + t + 256];
    __syncthreads();

    // top-16 via shuffle argmax (tie -> lower index)
    for (int kk = 0; kk < KSEL; kk++) {
        float v = sc[t]; int idx = t;
        float v2 = sc[t + 256];
        if (v2 > v) { v = v2; idx = t + 256; }
        #pragma unroll
        for (int o = 16; o > 0; o >>= 1) {
            float ov = __shfl_down_sync(0xffffffffu, v, o);
            int   oi = __shfl_down_sync(0xffffffffu, idx, o);
            if (ov > v || (ov == v && oi < idx)) { v = ov; idx = oi; }
        }
        if (lane == 0) { wv[wid] = v; wi[wid] = idx; }
        __syncthreads();
        if (t == 0) {
            float bv = wv[0]; int bi = wi[0];
            #pragma unroll
            for (int ww = 1; ww < 8; ww++) {
                if (wv[ww] > bv || (wv[ww] == bv && wi[ww] < bi)) {
                    bv = wv[ww]; bi = wi[ww];
                }
            }
            sel_idx[kk] = bi;
            sel_val[kk] = bv;
            sc[bi] = -INFINITY;
        }
        __syncthreads();
    }
    if (t == 0) {
        float m = sel_val[0];
        float sum = 0.f;
        for (int kk = 0; kk < KSEL; kk++) { w[kk] = expf(sel_val[kk] - m); sum += w[kk]; }
        float inv = 1.0f / sum;
        for (int kk = 0; kk < KSEL; kk++) w[kk] *= inv;
    }
    __syncthreads();

    if (t < KSEL) idx_out[(long)token * KSEL + t] = (float)sel_idx[t];
    if (t < NBASIS) {
        float c = 0.f;
        for (int kk = 0; kk < KSEL; kk++) c += w[kk] * ncoords[(long)sel_idx[kk] * NBASIS + t];
        coords_out[(long)token * NBASIS + t] = c;
    }

    float a0 = x[(long)token * DD + t];
    float a1 = x[(long)token * DD + t + 256];
    #pragma unroll
    for (int kk = 0; kk < KSEL; kk++) {
        a0 += w[kk] * emb[(long)sel_idx[kk] * DD + t];
        a1 += w[kk] * emb[(long)sel_idx[kk] * DD + t + 256];
    }
    x1[(long)token * DD + t]       = a0;
    x1[(long)token * DD + t + 256] = a1;

    // LN2 -> bf16
    __syncthreads();
    sc[t]   = a0 + a1;
    red2[t] = a0 * a0 + a1 * a1;
    __syncthreads();
    for (int s = 128; s > 0; s >>= 1) {
        if (t < s) { sc[t] += sc[t + s]; red2[t] += red2[t + s]; }
        __syncthreads();
    }
    float mu  = sc[0] * (1.0f / DD);
    float var = red2[0] * (1.0f / DD) - mu * mu;
    float r = rsqrtf(var + LN_EPS);
    n2bf[(long)token * DD + t]       = __float2bfloat16((a0 - mu) * r * ln2g[t] + ln2b[t]);
    n2bf[(long)token * DD + t + 256] = __float2bfloat16((a1 - mu) * r * ln2g[t + 256] + ln2b[t + 256]);
}

// ---------------- combine ----------------
__global__ void combine_kernel(const float* __restrict__ P,
                               const float* __restrict__ coords,
                               __nv_bfloat16* __restrict__ HHo)
{
    int token = blockIdx.x;
    int r = threadIdx.x;
    __shared__ float c[NBASIS];
    if (r < NBASIS) c[r] = coords[(long)token * NBASIS + r];
    __syncthreads();
    float h = 0.f;
    #pragma unroll
    for (int n = 0; n < NBASIS; n++) h += c[n] * P[(long)token * 512 + n * RANK + r];
    #pragma unroll
    for (int n = 0; n < NBASIS; n++)
        HHo[(long)token * 512 + n * RANK + r] = __float2bfloat16(c[n] * h);
}

// ---------------- launch ----------------
extern "C" void kernel_launch(void* const* d_in, const int* in_sizes, int n_in,
                              void* d_out, int out_size)
{
    const float* x    = (const float*)d_in[0];
    const float* emb  = (const float*)d_in[1];
    const float* Wq   = (const float*)d_in[2];
    const float* bq   = (const float*)d_in[3];
    const float* Wk   = (const float*)d_in[4];
    const float* bk   = (const float*)d_in[5];
    const float* Wv   = (const float*)d_in[6];
    const float* bv   = (const float*)d_in[7];
    const float* Wg   = (const float*)d_in[8];
    const float* bg   = (const float*)d_in[9];
    const float* bA   = (const float*)d_in[10];
    const float* bBf  = (const float*)d_in[11];
    const float* ncd  = (const float*)d_in[12];
    const float* Wd   = (const float*)d_in[13];
    const float* bd   = (const float*)d_in[14];
    const float* ln1g = (const float*)d_in[15];
    const float* ln1b = (const float*)d_in[16];
    const float* ln2g = (const float*)d_in[17];
    const float* ln2b = (const float*)d_in[18];

    float* out     = (float*)d_out;
    float* out_idx = out + (long)NTOK * DD;

    float *normed, *q, *k, *v, *ctx, *ts, *cs, *x1, *tcv, *P;
    __nv_bfloat16 *n2bf, *HHbf, *h2bf, *btA, *btB, *btW;
    cudaGetSymbolAddress((void**)&normed, g_normed);
    cudaGetSymbolAddress((void**)&q, g_q);
    cudaGetSymbolAddress((void**)&k, g_k);
    cudaGetSymbolAddress((void**)&v, g_v);
    cudaGetSymbolAddress((void**)&ctx, g_ctx);
    cudaGetSymbolAddress((void**)&ts, g_ts);
    cudaGetSymbolAddress((void**)&cs, g_cs);
    cudaGetSymbolAddress((void**)&x1, g_x1);
    cudaGetSymbolAddress((void**)&tcv, g_tc);
    cudaGetSymbolAddress((void**)&P, g_P);
    cudaGetSymbolAddress((void**)&n2bf, g_n2bf);
    cudaGetSymbolAddress((void**)&HHbf, g_HHbf);
    cudaGetSymbolAddress((void**)&h2bf, g_h2bf);
    cudaGetSymbolAddress((void**)&btA, g_btA);
    cudaGetSymbolAddress((void**)&btB, g_btB);
    cudaGetSymbolAddress((void**)&btW, g_btW);

    // attn_fused needs >48KB dynamic smem
    static int smem_set = 0;
    const int ATTN_SMEM = 4 * 64 * FT * (int)sizeof(float);   // 69632
    if (!smem_set) {
        cudaFuncSetAttribute(attn_fused,
                             cudaFuncAttributeMaxDynamicSharedMemorySize,
                             ATTN_SMEM);
        smem_set = 1;
    }

    // FFN weight prep
    prep_weights<<<2304, dim3(32, 8)>>>(bA, bBf, Wd, btA, btB, btW);

    // 1. LN1 (fp32)
    ln_kernel<<<NTOK, 256>>>(x, ln1g, ln1b, normed);

    // 2. QKV (fp32)
    qkv128<<<dim3(DD / 64, NTOK / 128, 3), 256>>>(normed, Wq, Wk, Wv,
                                                  bq, bk, bv, q, k, v);

    // 3. fused flash attention, 64-row tiles + register prefetch
    attn_fused<<<dim3(BB * HH_, SS / 64), 256, ATTN_SMEM>>>(q, k, v, ctx);

    // 4. neuron scores (fp32, z=2)
    ns128<<<dim3(NNEUR / 64, NTOK / 128, 2), 256>>>(normed, ctx, emb, ts, cs);

    // 5. fused gate + topk + residual + coords + LN2
    topk_fused<<<NTOK, 256>>>(ts, cs, normed, ctx, Wg, bg, x, emb, ncd,
                              ln2g, ln2b, x1, n2bf, tcv, out_idx);

    // 7. P = n2 @ A_n (bf16 mma, batched over n)
    mma_gemm<<<dim3(1, NTOK / MT, NBASIS), 256>>>(
        n2bf, DD, 0, btA, DD, (long long)RANK * DD, DD,
        P, NBASIS * RANK, RANK, nullptr, nullptr, 0, 0);

    // 8. combine -> HH (bf16)
    combine_kernel<<<NTOK, 64>>>(P, tcv, HHbf);

    // 9. h2 = gelu(HH @ B_flat) (bf16 mma, 128x128 tiles)
    mma_gemm_n128<<<dim3(DFF / 128, NTOK / 128), 256>>>(
        HHbf, NBASIS * RANK, btB, NBASIS * RANK, NBASIS * RANK, h2bf, DFF);

    // 10. out = h2 @ Wd + bd + x1 (bf16 mma)
    mma_gemm<<<dim3(DD / NT, NTOK / MT, 1), 256>>>(
        h2bf, DFF, 0, btW, DFF, 0, DFF,
        out, DD, 0, bd, x1, DD, 2);
}